// round 6
// baseline (speedup 1.0000x reference)
#include <cuda_runtime.h>
#include <cuda_fp16.h>

#define BB 16
#define CC 3
#define HH 256
#define WW 256
#define MM 100
#define HW (HH * WW)

// Quad-packed fp16 image, zero-halo padded, two planes (same as R5).
#define NE 259
#define NR 259
#define STR01 264
#define STR2  272
__device__ uint4 g_c01[BB * 260 * STR01];
__device__ uint2 g_c2[BB * 260 * STR2];

__device__ __forceinline__ unsigned packh2(float a, float b) {
    __half2 h = __halves2half2(__float2half(a), __float2half(b));
    return *reinterpret_cast<unsigned*>(&h);
}

__global__ void pack_kernel(const float* __restrict__ x) {
    int ex = blockIdx.x * blockDim.x + threadIdx.x;
    if (ex >= NE) return;
    int ey = blockIdx.y;
    int b = blockIdx.z;
    int x0 = ex - 2, y0 = ey - 2;

    float c[2][2][3];
#pragma unroll
    for (int dy = 0; dy < 2; dy++)
#pragma unroll
        for (int dx = 0; dx < 2; dx++) {
            int yy = y0 + dy, xx = x0 + dx;
            bool v = ((unsigned)yy < (unsigned)HH) && ((unsigned)xx < (unsigned)WW);
            const float* p = x + (size_t)b * CC * HW + yy * WW + xx;
            c[dy][dx][0] = v ? p[0] : 0.0f;
            c[dy][dx][1] = v ? p[HW] : 0.0f;
            c[dy][dx][2] = v ? p[2 * HW] : 0.0f;
        }

    uint4 q;
    q.x = packh2(c[0][0][0], c[0][0][1]);
    q.y = packh2(c[0][1][0], c[0][1][1]);
    q.z = packh2(c[1][0][0], c[1][0][1]);
    q.w = packh2(c[1][1][0], c[1][1][1]);
    g_c01[(b * 260 + ey) * STR01 + ex] = q;

    uint2 r;
    r.x = packh2(c[0][0][2], c[0][1][2]);   // c2 row y0:  (lo, hi)
    r.y = packh2(c[1][0][2], c[1][1][2]);   // c2 row y0+1:(lo, hi)
    g_c2[(b * 260 + ey) * STR2 + ex] = r;
}

__device__ __forceinline__ __half2 u2h(unsigned u) {
    return *reinterpret_cast<const __half2*>(&u);
}

// Warp = 4x4 output tile x 2 ky-halves (lane pairs). Block = 8x8 tile.
__global__ void __launch_bounds__(128, 12) stn_kernel(const float* __restrict__ theta,
                                                      float* __restrict__ out) {
    int tid = threadIdx.x;
    int half = tid & 1;
    int p = (tid >> 1) & 15;
    int w = tid >> 5;
    int i = blockIdx.y * 8 + ((w >> 1) << 2) + (p >> 2);
    int j = blockIdx.x * 8 + ((w & 1) << 2) + (p & 3);
    int b = blockIdx.z;
    bool valid = (i < MM) && (j < MM);
    i = min(i, MM - 1);
    j = min(j, MM - 1);

    const float* th = theta + b * 6;
    float t00 = __ldg(th + 0), t01 = __ldg(th + 1), t02 = __ldg(th + 2);
    float t10 = __ldg(th + 3), t11 = __ldg(th + 4), t12 = __ldg(th + 5);

    float lx = (j + 0.5f) * (2.0f / MM) - 1.0f;
    float ly = (i + 0.5f) * (2.0f / MM) - 1.0f;
    float gx = fmaf(t00, lx, fmaf(t01, ly, t02));
    float gy = fmaf(t10, lx, fmaf(t11, ly, t12));

    // pixel-space base, pre-biased by +2 into padded entry index space
    float ixb = fmaf(gx, 0.5f * WW, 0.5f * WW - 0.5f + 2.0f);
    float iyb = fmaf(gy, 0.5f * HH, 0.5f * HH - 0.5f + 2.0f);

    const float cstep = (0.5f * WW) / (6.0f * 99.0f);
    float ux = t00 * cstep, uy = t10 * cstep;
    float vx = t01 * cstep, vy = t11 * cstep;

    const float wkx[11] = {0.00386592f, 0.02856550f, 0.13533528f, 0.41111229f,
                           0.80073740f, 1.0f,        0.80073740f, 0.41111229f,
                           0.13533528f, 0.02856550f, 0.00386592f};
    const float wsum = 3.75923278f;
    const float inv = 1.0f / (wsum * wsum);

    const uint4* __restrict__ base01 = g_c01 + b * (260 * STR01);
    const uint2* __restrict__ base2 = g_c2 + b * (260 * STR2);

    float acc0 = 0.0f, acc1 = 0.0f, acc2 = 0.0f;

#pragma unroll 1
    for (int ky = half; ky < 11; ky += 2) {
        float dky = (float)(ky - 5);
        float dd = dky * (1.0f / 6.0f);
        float wyk = expf(-8.0f * dd * dd);
        float ixr = fmaf(dky, vx, ixb);
        float iyr = fmaf(dky, vy, iyb);
#pragma unroll
        for (int kx = 0; kx < 11; kx++) {
            float dkx = (float)(kx - 5);
            float ix = fmaf(dkx, ux, ixr);
            float iy = fmaf(dkx, uy, iyr);

            float x0f = floorf(ix);
            float y0f = floorf(iy);
            float fx = ix - x0f;
            float fy = iy - y0f;
            int xq = min(max((int)x0f, 0), NE - 1);
            int yq = min(max((int)y0f, 0), NR - 1);

            uint4 q = base01[yq * STR01 + xq];
            uint2 r = base2[yq * STR2 + xq];

            float wgt = wyk * wkx[kx];
            float a0 = fmaf(-wgt, fy, wgt);   // wgt*(1-fy)
            float a1 = wgt * fy;
            float w00 = fmaf(-a0, fx, a0);    // a0*(1-fx)
            float w01 = a0 * fx;
            float w10 = fmaf(-a1, fx, a1);
            float w11 = a1 * fx;

            // c0,c1: 4 broadcast-weight HFMA2 into one half2 partial
            __half2 s01 = __hmul2(__float2half2_rn(w00), u2h(q.x));
            s01 = __hfma2(__float2half2_rn(w01), u2h(q.y), s01);
            s01 = __hfma2(__float2half2_rn(w10), u2h(q.z), s01);
            s01 = __hfma2(__float2half2_rn(w11), u2h(q.w), s01);

            // c2: packed-weight HFMA2 (lanes = lo/hi corner pair)
            __half2 s2 = __hmul2(__floats2half2_rn(w00, w01), u2h(r.x));
            s2 = __hfma2(__floats2half2_rn(w10, w11), u2h(r.y), s2);

            float2 f01 = __half22float2(s01);
            acc0 += f01.x;
            acc1 += f01.y;
            float2 f2 = __half22float2(s2);
            acc2 += f2.x + f2.y;
        }
    }

    acc0 += __shfl_xor_sync(0xffffffff, acc0, 1);
    acc1 += __shfl_xor_sync(0xffffffff, acc1, 1);
    acc2 += __shfl_xor_sync(0xffffffff, acc2, 1);

    if (half == 0 && valid) {
        int r = i * MM + j;
        float* ob = out + b * (CC * MM * MM) + r;
        ob[0]           = acc0 * inv;
        ob[MM * MM]     = acc1 * inv;
        ob[2 * MM * MM] = acc2 * inv;
    }
}

extern "C" void kernel_launch(void* const* d_in, const int* in_sizes, int n_in,
                              void* d_out, int out_size) {
    const float* x = (const float*)d_in[0];
    const float* th = (const float*)d_in[1];
    if (n_in >= 2 && in_sizes[0] == 96) {
        x = (const float*)d_in[1];
        th = (const float*)d_in[0];
    }
    float* out = (float*)d_out;

    {
        int tpb = 256;
        dim3 grid((NE + tpb - 1) / tpb, NR, BB);
        pack_kernel<<<grid, tpb>>>(x);
    }
    {
        dim3 grid((MM + 7) / 8, (MM + 7) / 8, BB);
        stn_kernel<<<grid, 128>>>(th, out);
    }
    (void)out_size;
}

// round 7
// speedup vs baseline: 1.2314x; 1.2314x over previous
#include <cuda_runtime.h>
#include <cuda_fp16.h>

#define BB 16
#define CC 3
#define HH 256
#define WW 256
#define MM 100
#define HW (HH * WW)

// Quad-packed fp16 image, zero-halo padded, two planes (layout as R5,
// but STR2 == STR01 so both planes share one linear entry index).
#define NE 259
#define NR 259
#define STRE 264
__device__ uint4 g_c01[BB * 260 * STRE];
__device__ uint2 g_c2[BB * 260 * STRE];

__constant__ float c_wk[11] = {0.00386592f, 0.02856550f, 0.13533528f, 0.41111229f,
                               0.80073740f, 1.0f,        0.80073740f, 0.41111229f,
                               0.13533528f, 0.02856550f, 0.00386592f};

__device__ __forceinline__ unsigned packh2(float a, float b) {
    __half2 h = __halves2half2(__float2half(a), __float2half(b));
    return *reinterpret_cast<unsigned*>(&h);
}

__global__ void pack_kernel(const float* __restrict__ x) {
    int ex = blockIdx.x * blockDim.x + threadIdx.x;
    if (ex >= NE) return;
    int ey = blockIdx.y;
    int b = blockIdx.z;
    int x0 = ex - 2, y0 = ey - 2;

    float c[2][2][3];
#pragma unroll
    for (int dy = 0; dy < 2; dy++)
#pragma unroll
        for (int dx = 0; dx < 2; dx++) {
            int yy = y0 + dy, xx = x0 + dx;
            bool v = ((unsigned)yy < (unsigned)HH) && ((unsigned)xx < (unsigned)WW);
            const float* p = x + (size_t)b * CC * HW + yy * WW + xx;
            c[dy][dx][0] = v ? p[0] : 0.0f;
            c[dy][dx][1] = v ? p[HW] : 0.0f;
            c[dy][dx][2] = v ? p[2 * HW] : 0.0f;
        }

    uint4 q;
    q.x = packh2(c[0][0][0], c[0][0][1]);
    q.y = packh2(c[0][1][0], c[0][1][1]);
    q.z = packh2(c[1][0][0], c[1][0][1]);
    q.w = packh2(c[1][1][0], c[1][1][1]);
    g_c01[(b * 260 + ey) * STRE + ex] = q;

    uint2 r;
    r.x = packh2(c[0][0][2], c[0][1][2]);   // c2 row y0:   (lo, hi)
    r.y = packh2(c[1][0][2], c[1][1][2]);   // c2 row y0+1: (lo, hi)
    g_c2[(b * 260 + ey) * STRE + ex] = r;
}

__device__ __forceinline__ __half2 u2h(unsigned u) {
    return *reinterpret_cast<const __half2*>(&u);
}

// Warp = 4x4 output tile x 2 ky-halves (lane pairs). Block = 8x8 tile.
__global__ void __launch_bounds__(128, 10) stn_kernel(const float* __restrict__ theta,
                                                      float* __restrict__ out) {
    int tid = threadIdx.x;
    int half = tid & 1;
    int p = (tid >> 1) & 15;
    int w = tid >> 5;
    int i = blockIdx.y * 8 + ((w >> 1) << 2) + (p >> 2);
    int j = blockIdx.x * 8 + ((w & 1) << 2) + (p & 3);
    int b = blockIdx.z;
    bool valid = (i < MM) && (j < MM);
    i = min(i, MM - 1);
    j = min(j, MM - 1);

    const float* th = theta + b * 6;
    float t00 = __ldg(th + 0), t01 = __ldg(th + 1), t02 = __ldg(th + 2);
    float t10 = __ldg(th + 3), t11 = __ldg(th + 4), t12 = __ldg(th + 5);

    float lx = (j + 0.5f) * (2.0f / MM) - 1.0f;
    float ly = (i + 0.5f) * (2.0f / MM) - 1.0f;
    float gx = fmaf(t00, lx, fmaf(t01, ly, t02));
    float gy = fmaf(t10, lx, fmaf(t11, ly, t12));

    // pixel-space base, pre-biased by +2 into padded entry index space
    float ixb = fmaf(gx, 0.5f * WW, 0.5f * WW - 0.5f + 2.0f);
    float iyb = fmaf(gy, 0.5f * HH, 0.5f * HH - 0.5f + 2.0f);

    const float cstep = (0.5f * WW) / (6.0f * 99.0f);
    float ux = t00 * cstep, uy = t10 * cstep;
    float vx = t01 * cstep, vy = t11 * cstep;

    const float wsum = 3.75923278f;
    const float inv = 1.0f / (wsum * wsum);

    const uint4* __restrict__ base01 = g_c01 + b * (260 * STRE);
    const uint2* __restrict__ base2 = g_c2 + b * (260 * STRE);

    float acc0 = 0.0f, acc1 = 0.0f, acc2 = 0.0f;
    const __half2 hz = __float2half2_rn(0.0f);

#pragma unroll 1
    for (int ky = half; ky < 11; ky += 2) {
        float dky = (float)(ky - 5);
        float wyk = c_wk[ky];
        float ixr = fmaf(dky, vx, ixb);
        float iyr = fmaf(dky, vy, iyb);

        // row-persistent fp16 accumulators (ping-pong halves the dep chain)
        __half2 ra = hz, rb = hz, r2 = hz;

#pragma unroll
        for (int kx = 0; kx < 11; kx++) {
            const float wkx_lit[11] = {0.00386592f, 0.02856550f, 0.13533528f,
                                       0.41111229f, 0.80073740f, 1.0f,
                                       0.80073740f, 0.41111229f, 0.13533528f,
                                       0.02856550f, 0.00386592f};
            float dkx = (float)(kx - 5);
            float ix = fmaf(dkx, ux, ixr);
            float iy = fmaf(dkx, uy, iyr);

            float x0f = floorf(ix);
            float y0f = floorf(iy);
            float fx = ix - x0f;
            float fy = iy - y0f;
            int xq = min(max((int)x0f, 0), NE - 1);
            int yq = min(max((int)y0f, 0), NR - 1);
            int idx = yq * STRE + xq;

            uint4 q = base01[idx];
            uint2 r = base2[idx];

            float wgt = wyk * wkx_lit[kx];
            float a0 = fmaf(-wgt, fy, wgt);   // wgt*(1-fy)
            float a1 = wgt * fy;
            float w00 = fmaf(-a0, fx, a0);    // a0*(1-fx)
            float w01 = a0 * fx;
            float w10 = fmaf(-a1, fx, a1);
            float w11 = a1 * fx;

            // c0,c1: broadcast-weight HFMA2 into ping-pong accumulators
            ra = __hfma2(__float2half2_rn(w00), u2h(q.x), ra);
            rb = __hfma2(__float2half2_rn(w01), u2h(q.y), rb);
            ra = __hfma2(__float2half2_rn(w10), u2h(q.z), ra);
            rb = __hfma2(__float2half2_rn(w11), u2h(q.w), rb);

            // c2: packed-weight HFMA2 (lanes = lo/hi corner pair)
            r2 = __hfma2(__floats2half2_rn(w00, w01), u2h(r.x), r2);
            r2 = __hfma2(__floats2half2_rn(w10, w11), u2h(r.y), r2);
        }

        // flush row to fp32
        float2 fa = __half22float2(ra);
        float2 fb = __half22float2(rb);
        float2 f2 = __half22float2(r2);
        acc0 += fa.x + fb.x;
        acc1 += fa.y + fb.y;
        acc2 += f2.x + f2.y;
    }

    acc0 += __shfl_xor_sync(0xffffffff, acc0, 1);
    acc1 += __shfl_xor_sync(0xffffffff, acc1, 1);
    acc2 += __shfl_xor_sync(0xffffffff, acc2, 1);

    if (half == 0 && valid) {
        int r = i * MM + j;
        float* ob = out + b * (CC * MM * MM) + r;
        ob[0]           = acc0 * inv;
        ob[MM * MM]     = acc1 * inv;
        ob[2 * MM * MM] = acc2 * inv;
    }
}

extern "C" void kernel_launch(void* const* d_in, const int* in_sizes, int n_in,
                              void* d_out, int out_size) {
    const float* x = (const float*)d_in[0];
    const float* th = (const float*)d_in[1];
    if (n_in >= 2 && in_sizes[0] == 96) {
        x = (const float*)d_in[1];
        th = (const float*)d_in[0];
    }
    float* out = (float*)d_out;

    {
        int tpb = 256;
        dim3 grid((NE + tpb - 1) / tpb, NR, BB);
        pack_kernel<<<grid, tpb>>>(x);
    }
    {
        dim3 grid((MM + 7) / 8, (MM + 7) / 8, BB);
        stn_kernel<<<grid, 128>>>(th, out);
    }
    (void)out_size;
}

// round 8
// speedup vs baseline: 1.3207x; 1.0725x over previous
#include <cuda_runtime.h>
#include <cuda_fp16.h>

#define BB 16
#define CC 3
#define HH 256
#define WW 256
#define MM 100
#define HW (HH * WW)

// Quad-packed fp16 image, zero-halo padded, two planes sharing one index.
#define NE 259
#define NR 259
#define STRE 264
__device__ uint4 g_c01[BB * 260 * STRE];
__device__ uint2 g_c2[BB * 260 * STRE];

__constant__ float c_wk[11] = {0.00386592f, 0.02856550f, 0.13533528f, 0.41111229f,
                               0.80073740f, 1.0f,        0.80073740f, 0.41111229f,
                               0.13533528f, 0.02856550f, 0.00386592f};

__device__ __forceinline__ unsigned packh2(float a, float b) {
    __half2 h = __halves2half2(__float2half(a), __float2half(b));
    return *reinterpret_cast<unsigned*>(&h);
}

// Shfl-based pack: block = 9 warps, one padded row (ey, b) per block.
// Warp w, lane l: loads column c = w*31 + l - 2 (rows y0, y0+1, 3 channels,
// coalesced); the x0-corner column (c-1) comes from lane l-1 via shfl_up.
// Lanes 1..31 emit entry ex = c + 1. Entry ex has corners cols (ex-2, ex-1).
__global__ void __launch_bounds__(288) pack_kernel(const float* __restrict__ x) {
    int w = threadIdx.x >> 5;
    int l = threadIdx.x & 31;
    int ey = blockIdx.y;
    int b = blockIdx.z;
    int c = w * 31 + l - 2;        // this thread's column (may be OOB)
    int y0 = ey - 2;

    float v[6] = {0.f, 0.f, 0.f, 0.f, 0.f, 0.f};
    bool cx = ((unsigned)c < (unsigned)WW);
    const float* xb = x + (size_t)b * CC * HW + c;
    if (cx && (unsigned)y0 < (unsigned)HH) {
        const float* p = xb + y0 * WW;
        v[0] = p[0]; v[1] = p[HW]; v[2] = p[2 * HW];
    }
    if (cx && (unsigned)(y0 + 1) < (unsigned)HH) {
        const float* p = xb + (y0 + 1) * WW;
        v[3] = p[0]; v[4] = p[HW]; v[5] = p[2 * HW];
    }

    float n[6];
#pragma unroll
    for (int k = 0; k < 6; k++)
        n[k] = __shfl_up_sync(0xffffffffu, v[k], 1);

    int ex = c + 1;
    if (l >= 1 && (unsigned)ex <= (unsigned)(NE - 1)) {
        uint4 q;
        q.x = packh2(n[0], n[1]);   // (y0,   ex-2): c0,c1
        q.y = packh2(v[0], v[1]);   // (y0,   ex-1)
        q.z = packh2(n[3], n[4]);   // (y0+1, ex-2)
        q.w = packh2(v[3], v[4]);   // (y0+1, ex-1)
        int idx = (b * 260 + ey) * STRE + ex;
        g_c01[idx] = q;
        uint2 r;
        r.x = packh2(n[2], v[2]);   // c2 row y0:   (lo, hi)
        r.y = packh2(n[5], v[5]);   // c2 row y0+1: (lo, hi)
        g_c2[idx] = r;
    }
}

__device__ __forceinline__ __half2 u2h(unsigned u) {
    return *reinterpret_cast<const __half2*>(&u);
}

// Warp = 4x4 output tile x 2 ky-halves (lane pairs). Block = 8x8 tile.
__global__ void __launch_bounds__(128, 12) stn_kernel(const float* __restrict__ theta,
                                                      float* __restrict__ out) {
    int tid = threadIdx.x;
    int half = tid & 1;
    int p = (tid >> 1) & 15;
    int w = tid >> 5;
    int i = blockIdx.y * 8 + ((w >> 1) << 2) + (p >> 2);
    int j = blockIdx.x * 8 + ((w & 1) << 2) + (p & 3);
    int b = blockIdx.z;
    bool valid = (i < MM) && (j < MM);
    i = min(i, MM - 1);
    j = min(j, MM - 1);

    const float* th = theta + b * 6;
    float t00 = __ldg(th + 0), t01 = __ldg(th + 1), t02 = __ldg(th + 2);
    float t10 = __ldg(th + 3), t11 = __ldg(th + 4), t12 = __ldg(th + 5);

    float lx = (j + 0.5f) * (2.0f / MM) - 1.0f;
    float ly = (i + 0.5f) * (2.0f / MM) - 1.0f;
    float gx = fmaf(t00, lx, fmaf(t01, ly, t02));
    float gy = fmaf(t10, lx, fmaf(t11, ly, t12));

    float ixb = fmaf(gx, 0.5f * WW, 0.5f * WW - 0.5f + 2.0f);
    float iyb = fmaf(gy, 0.5f * HH, 0.5f * HH - 0.5f + 2.0f);

    const float cstep = (0.5f * WW) / (6.0f * 99.0f);
    float ux = t00 * cstep, uy = t10 * cstep;
    float vx = t01 * cstep, vy = t11 * cstep;

    const float wsum = 3.75923278f;
    const float inv = 1.0f / (wsum * wsum);

    const uint4* __restrict__ base01 = g_c01 + b * (260 * STRE);
    const uint2* __restrict__ base2 = g_c2 + b * (260 * STRE);

    float acc0 = 0.0f, acc1 = 0.0f, acc2 = 0.0f;
    const __half2 hz = __float2half2_rn(0.0f);

#pragma unroll 1
    for (int ky = half; ky < 11; ky += 2) {
        float dky = (float)(ky - 5);
        float wyk = c_wk[ky];
        float ixr = fmaf(dky, vx, ixb);
        float iyr = fmaf(dky, vy, iyb);

        __half2 ra = hz, rb = hz, r2 = hz;

#pragma unroll
        for (int kx = 0; kx < 11; kx++) {
            const float wkx_lit[11] = {0.00386592f, 0.02856550f, 0.13533528f,
                                       0.41111229f, 0.80073740f, 1.0f,
                                       0.80073740f, 0.41111229f, 0.13533528f,
                                       0.02856550f, 0.00386592f};
            float dkx = (float)(kx - 5);
            float ix = fmaf(dkx, ux, ixr);
            float iy = fmaf(dkx, uy, iyr);

            float x0f = floorf(ix);
            float y0f = floorf(iy);
            float fx = ix - x0f;
            float fy = iy - y0f;
            int xq = min(max((int)x0f, 0), NE - 1);
            int yq = min(max((int)y0f, 0), NR - 1);
            int idx = yq * STRE + xq;

            uint4 q = base01[idx];
            uint2 r = base2[idx];

            float wgt = wyk * wkx_lit[kx];
            float a0 = fmaf(-wgt, fy, wgt);
            float a1 = wgt * fy;
            float w00 = fmaf(-a0, fx, a0);
            float w01 = a0 * fx;
            float w10 = fmaf(-a1, fx, a1);
            float w11 = a1 * fx;

            ra = __hfma2(__float2half2_rn(w00), u2h(q.x), ra);
            rb = __hfma2(__float2half2_rn(w01), u2h(q.y), rb);
            ra = __hfma2(__float2half2_rn(w10), u2h(q.z), ra);
            rb = __hfma2(__float2half2_rn(w11), u2h(q.w), rb);

            r2 = __hfma2(__floats2half2_rn(w00, w01), u2h(r.x), r2);
            r2 = __hfma2(__floats2half2_rn(w10, w11), u2h(r.y), r2);
        }

        float2 fa = __half22float2(ra);
        float2 fb = __half22float2(rb);
        float2 f2 = __half22float2(r2);
        acc0 += fa.x + fb.x;
        acc1 += fa.y + fb.y;
        acc2 += f2.x + f2.y;
    }

    acc0 += __shfl_xor_sync(0xffffffff, acc0, 1);
    acc1 += __shfl_xor_sync(0xffffffff, acc1, 1);
    acc2 += __shfl_xor_sync(0xffffffff, acc2, 1);

    if (half == 0 && valid) {
        int r = i * MM + j;
        float* ob = out + b * (CC * MM * MM) + r;
        ob[0]           = acc0 * inv;
        ob[MM * MM]     = acc1 * inv;
        ob[2 * MM * MM] = acc2 * inv;
    }
}

extern "C" void kernel_launch(void* const* d_in, const int* in_sizes, int n_in,
                              void* d_out, int out_size) {
    const float* x = (const float*)d_in[0];
    const float* th = (const float*)d_in[1];
    if (n_in >= 2 && in_sizes[0] == 96) {
        x = (const float*)d_in[1];
        th = (const float*)d_in[0];
    }
    float* out = (float*)d_out;

    {
        dim3 grid(1, NR, BB);      // 9 warps cover 259 entries per row
        pack_kernel<<<grid, 288>>>(x);
    }
    {
        dim3 grid((MM + 7) / 8, (MM + 7) / 8, BB);
        stn_kernel<<<grid, 128>>>(th, out);
    }
    (void)out_size;
}

// round 9
// speedup vs baseline: 1.7425x; 1.3194x over previous
#include <cuda_runtime.h>
#include <cuda_fp16.h>

#define BB 16
#define CC 3
#define HH 256
#define WW 256
#define MM 100
#define HW (HH * WW)

// Quad-packed fp16 image, zero-halo padded, two planes sharing one index.
#define NE 259
#define NR 259
#define STRE 264
__device__ uint4 g_c01[BB * 260 * STRE];
__device__ uint2 g_c2[BB * 260 * STRE];

__constant__ float c_wk[11] = {0.00386592f, 0.02856550f, 0.13533528f, 0.41111229f,
                               0.80073740f, 1.0f,        0.80073740f, 0.41111229f,
                               0.13533528f, 0.02856550f, 0.00386592f};

__device__ __forceinline__ unsigned packh2(float a, float b) {
    __half2 h = __halves2half2(__float2half(a), __float2half(b));
    return *reinterpret_cast<unsigned*>(&h);
}

// Shfl-based pack: block = 9 warps, one padded row (ey, b) per block.
__global__ void __launch_bounds__(288) pack_kernel(const float* __restrict__ x) {
    int w = threadIdx.x >> 5;
    int l = threadIdx.x & 31;
    int ey = blockIdx.y;
    int b = blockIdx.z;
    int c = w * 31 + l - 2;
    int y0 = ey - 2;

    float v[6] = {0.f, 0.f, 0.f, 0.f, 0.f, 0.f};
    bool cx = ((unsigned)c < (unsigned)WW);
    const float* xb = x + (size_t)b * CC * HW + c;
    if (cx && (unsigned)y0 < (unsigned)HH) {
        const float* p = xb + y0 * WW;
        v[0] = p[0]; v[1] = p[HW]; v[2] = p[2 * HW];
    }
    if (cx && (unsigned)(y0 + 1) < (unsigned)HH) {
        const float* p = xb + (y0 + 1) * WW;
        v[3] = p[0]; v[4] = p[HW]; v[5] = p[2 * HW];
    }

    float n[6];
#pragma unroll
    for (int k = 0; k < 6; k++)
        n[k] = __shfl_up_sync(0xffffffffu, v[k], 1);

    int ex = c + 1;
    if (l >= 1 && (unsigned)ex <= (unsigned)(NE - 1)) {
        uint4 q;
        q.x = packh2(n[0], n[1]);
        q.y = packh2(v[0], v[1]);
        q.z = packh2(n[3], n[4]);
        q.w = packh2(v[3], v[4]);
        int idx = (b * 260 + ey) * STRE + ex;
        g_c01[idx] = q;
        uint2 r;
        r.x = packh2(n[2], v[2]);
        r.y = packh2(n[5], v[5]);
        g_c2[idx] = r;
    }
}

__device__ __forceinline__ __half2 u2h(unsigned u) {
    return *reinterpret_cast<const __half2*>(&u);
}

// Warp = 4x4 output tile x 2 ky-halves (lane pairs). Block = 8x8 tile.
__global__ void __launch_bounds__(128, 10) stn_kernel(const float* __restrict__ theta,
                                                      float* __restrict__ out) {
    int tid = threadIdx.x;
    int half = tid & 1;
    int p = (tid >> 1) & 15;
    int w = tid >> 5;
    int i = blockIdx.y * 8 + ((w >> 1) << 2) + (p >> 2);
    int j = blockIdx.x * 8 + ((w & 1) << 2) + (p & 3);
    int b = blockIdx.z;
    bool valid = (i < MM) && (j < MM);
    i = min(i, MM - 1);
    j = min(j, MM - 1);

    const float* th = theta + b * 6;
    float t00 = __ldg(th + 0), t01 = __ldg(th + 1), t02 = __ldg(th + 2);
    float t10 = __ldg(th + 3), t11 = __ldg(th + 4), t12 = __ldg(th + 5);

    float lx = (j + 0.5f) * (2.0f / MM) - 1.0f;
    float ly = (i + 0.5f) * (2.0f / MM) - 1.0f;
    float gx = fmaf(t00, lx, fmaf(t01, ly, t02));
    float gy = fmaf(t10, lx, fmaf(t11, ly, t12));

    float ixb = fmaf(gx, 0.5f * WW, 0.5f * WW - 0.5f + 2.0f);
    float iyb = fmaf(gy, 0.5f * HH, 0.5f * HH - 0.5f + 2.0f);

    const float cstep = (0.5f * WW) / (6.0f * 99.0f);
    float ux = t00 * cstep, uy = t10 * cstep;
    float vx = t01 * cstep, vy = t11 * cstep;

    const float wsum = 3.75923278f;
    const float inv = 1.0f / (wsum * wsum);

    const uint4* __restrict__ base01 = g_c01 + b * (260 * STRE);
    const uint2* __restrict__ base2 = g_c2 + b * (260 * STRE);

    float acc0 = 0.0f, acc1 = 0.0f, acc2 = 0.0f;
    const __half2 hz = __float2half2_rn(0.0f);

    // persistent cell cache: loads issue only when the cell index changes
    int idx_prev = -1;
    uint4 q = make_uint4(0u, 0u, 0u, 0u);
    uint2 r = make_uint2(0u, 0u);

#pragma unroll 1
    for (int ky = half; ky < 11; ky += 2) {
        float dky = (float)(ky - 5);
        float wyk = c_wk[ky];
        float ixr = fmaf(dky, vx, ixb);
        float iyr = fmaf(dky, vy, iyb);

        __half2 ra = hz, rb = hz, r2 = hz;

#pragma unroll
        for (int kx = 0; kx < 11; kx++) {
            const float wkx_lit[11] = {0.00386592f, 0.02856550f, 0.13533528f,
                                       0.41111229f, 0.80073740f, 1.0f,
                                       0.80073740f, 0.41111229f, 0.13533528f,
                                       0.02856550f, 0.00386592f};
            float dkx = (float)(kx - 5);
            float ix = fmaf(dkx, ux, ixr);
            float iy = fmaf(dkx, uy, iyr);

            float x0f = floorf(ix);
            float y0f = floorf(iy);
            float fx = ix - x0f;
            float fy = iy - y0f;
            int xq = min(max((int)x0f, 0), NE - 1);
            int yq = min(max((int)y0f, 0), NR - 1);
            int idx = yq * STRE + xq;

            // predicated loads: no BSSY, no L1 wavefronts when skipped.
            // Same idx -> regs already hold identical data (bit-exact reuse).
            const uint4* a01 = base01 + idx;
            const uint2* a2 = base2 + idx;
            asm("{\n\t"
                ".reg .pred p;\n\t"
                "setp.ne.s32 p, %8, %9;\n\t"
                "@p ld.global.nc.v4.u32 {%0,%1,%2,%3}, [%6];\n\t"
                "@p ld.global.nc.v2.u32 {%4,%5}, [%7];\n\t"
                "}"
                : "+r"(q.x), "+r"(q.y), "+r"(q.z), "+r"(q.w),
                  "+r"(r.x), "+r"(r.y)
                : "l"(a01), "l"(a2), "r"(idx), "r"(idx_prev));
            idx_prev = idx;

            float wgt = wyk * wkx_lit[kx];
            float a0 = fmaf(-wgt, fy, wgt);
            float a1 = wgt * fy;
            float w00 = fmaf(-a0, fx, a0);
            float w01 = a0 * fx;
            float w10 = fmaf(-a1, fx, a1);
            float w11 = a1 * fx;

            ra = __hfma2(__float2half2_rn(w00), u2h(q.x), ra);
            rb = __hfma2(__float2half2_rn(w01), u2h(q.y), rb);
            ra = __hfma2(__float2half2_rn(w10), u2h(q.z), ra);
            rb = __hfma2(__float2half2_rn(w11), u2h(q.w), rb);

            r2 = __hfma2(__floats2half2_rn(w00, w01), u2h(r.x), r2);
            r2 = __hfma2(__floats2half2_rn(w10, w11), u2h(r.y), r2);
        }

        float2 fa = __half22float2(ra);
        float2 fb = __half22float2(rb);
        float2 f2 = __half22float2(r2);
        acc0 += fa.x + fb.x;
        acc1 += fa.y + fb.y;
        acc2 += f2.x + f2.y;
    }

    acc0 += __shfl_xor_sync(0xffffffff, acc0, 1);
    acc1 += __shfl_xor_sync(0xffffffff, acc1, 1);
    acc2 += __shfl_xor_sync(0xffffffff, acc2, 1);

    if (half == 0 && valid) {
        int rr = i * MM + j;
        float* ob = out + b * (CC * MM * MM) + rr;
        ob[0]           = acc0 * inv;
        ob[MM * MM]     = acc1 * inv;
        ob[2 * MM * MM] = acc2 * inv;
    }
}

extern "C" void kernel_launch(void* const* d_in, const int* in_sizes, int n_in,
                              void* d_out, int out_size) {
    const float* x = (const float*)d_in[0];
    const float* th = (const float*)d_in[1];
    if (n_in >= 2 && in_sizes[0] == 96) {
        x = (const float*)d_in[1];
        th = (const float*)d_in[0];
    }
    float* out = (float*)d_out;

    {
        dim3 grid(1, NR, BB);
        pack_kernel<<<grid, 288>>>(x);
    }
    {
        dim3 grid((MM + 7) / 8, (MM + 7) / 8, BB);
        stn_kernel<<<grid, 128>>>(th, out);
    }
    (void)out_size;
}